// round 2
// baseline (speedup 1.0000x reference)
#include <cuda_runtime.h>
#include <math.h>

#define A_NUM 15
#define NUM_FG 128
#define RPN_BATCH_C 256
#define MAX_G 512

// Precomputed base anchors (BASE_SIZE=16, ratios {0.5,1,2}, scales {1,2,4,8,16})
// index a = ratio*5 + scale; each row = x1,y1,x2,y2
__constant__ float c_base[60] = {
    -3.5f,   2.f,  18.5f,  13.f,
   -15.f,   -4.f,  30.f,   19.f,
   -38.f,  -16.f,  53.f,   31.f,
   -84.f,  -40.f,  99.f,   55.f,
  -176.f,  -88.f, 191.f,  103.f,
     0.f,    0.f,  15.f,   15.f,
    -8.f,   -8.f,  23.f,   23.f,
   -24.f,  -24.f,  39.f,   39.f,
   -56.f,  -56.f,  71.f,   71.f,
  -120.f, -120.f, 135.f,  135.f,
     2.5f,  -3.f,  12.5f,  18.f,
    -3.f,  -14.f,  18.f,   29.f,
   -14.f,  -36.f,  29.f,   51.f,
   -36.f,  -80.f,  51.f,   95.f,
   -80.f, -168.f,  95.f,  183.f
};

// scratch (no dynamic allocation allowed)
__device__ int g_bp[2048];
__device__ int g_bn[2048];
__device__ int g_pp[2048];
__device__ int g_np[2048];
__device__ int g_params[4];

// ---------------------------------------------------------------------------
// K1: per-anchor pass. Writes anchors, bbox_targets, preliminary labels.
// Row-wise max/argmax over gts via cross-multiplication (no per-pair division).
// ---------------------------------------------------------------------------
__global__ void k_main(const float* __restrict__ gt, const float* __restrict__ meta,
                       float* __restrict__ out, int K, int c, int G) {
    __shared__ float4 s_gt[MAX_G];
    __shared__ float  s_area[MAX_G];
    for (int g = threadIdx.x; g < G; g += blockDim.x) {
        float4 b = reinterpret_cast<const float4*>(gt)[g];
        s_gt[g] = b;
        s_area[g] = (b.z - b.x + 1.0f) * (b.w - b.y + 1.0f);
    }
    __syncthreads();

    int k = blockIdx.x * blockDim.x + threadIdx.x;
    if (k >= K) return;

    float h = meta[0], w = meta[1];

    int a = k % A_NUM;
    int t = k / A_NUM;
    int j = t % c;
    int i = t / c;
    float sxf = (float)(j * 16);
    float syf = (float)(i * 16);
    float x1 = sxf + c_base[a * 4 + 0];
    float y1 = syf + c_base[a * 4 + 1];
    float x2 = sxf + c_base[a * 4 + 2];
    float y2 = syf + c_base[a * 4 + 3];

    // output 0: raw anchors
    reinterpret_cast<float4*>(out)[k] = make_float4(x1, y1, x2, y2);

    float*  lab = out + (size_t)8 * K;
    float4* tgt = reinterpret_cast<float4*>(out + (size_t)4 * K);

    bool inside = (x1 >= 0.f) && (y1 >= 0.f) && (x2 < w) && (y2 < h);
    if (!inside) {
        tgt[k] = make_float4(0.f, 0.f, 0.f, 0.f);
        lab[k] = -1.f;
        return;
    }

    float wm1 = w - 1.f, hm1 = h - 1.f;
    float cx1 = fminf(fmaxf(x1, 0.f), wm1);
    float cy1 = fminf(fmaxf(y1, 0.f), hm1);
    float cx2 = fminf(fmaxf(x2, 0.f), wm1);
    float cy2 = fminf(fmaxf(y2, 0.f), hm1);

    float areaA = (cx2 - cx1 + 1.f) * (cy2 - cy1 + 1.f);

    // track best (inter, denom) pair; compare via cross-multiplication.
    float bi = -1.f, bd = 1.f;
    int   bg = 0;
    #pragma unroll 4
    for (int g = 0; g < G; g++) {
        float4 b = s_gt[g];
        float iw = (fminf(cx2, b.z) - fmaxf(cx1, b.x)) + 1.f;
        float ih = (fminf(cy2, b.w) - fmaxf(cy1, b.y)) + 1.f;
        float inter = fmaxf(iw, 0.f) * fmaxf(ih, 0.f);
        float denom = (areaA + s_area[g]) - inter;
        if (inter * bd > bi * denom) { bi = inter; bd = denom; bg = g; }
    }

    float mo = __fdiv_rn(bi, bd);   // single IEEE division per anchor
    float l = -1.f;
    if (mo < 0.3f)  l = 0.f;
    if (mo >= 0.7f) l = 1.f;
    lab[k] = l;

    float4 gb = s_gt[bg];
    float ew = cx2 - cx1 + 1.f, eh = cy2 - cy1 + 1.f;
    float ecx = cx1 + 0.5f * ew, ecy = cy1 + 0.5f * eh;
    float gw = gb.z - gb.x + 1.f, gh = gb.w - gb.y + 1.f;
    float gcx = gb.x + 0.5f * gw, gcy = gb.y + 0.5f * gh;
    tgt[k] = make_float4(__fdiv_rn(gcx - ecx, ew),
                         __fdiv_rn(gcy - ecy, eh),
                         logf(__fdiv_rn(gw, ew)),
                         logf(__fdiv_rn(gh, eh)));
}

// ---------------------------------------------------------------------------
// K2: per-gt argmax over all anchors (one block per gt), first-index ties.
// Winner anchor's label is forced to 1.0.
// ---------------------------------------------------------------------------
__global__ void k_col(const float* __restrict__ gt, const float* __restrict__ meta,
                      float* __restrict__ out, int K, int c) {
    int g = blockIdx.x;
    float4 b = reinterpret_cast<const float4*>(gt)[g];
    float areaB = (b.z - b.x + 1.f) * (b.w - b.y + 1.f);
    float h = meta[0], w = meta[1];
    float wm1 = w - 1.f, hm1 = h - 1.f;

    float bi = -1.f, bd = 1.f;
    int   bk = 0;

    for (int k = threadIdx.x; k < K; k += blockDim.x) {
        int a = k % A_NUM;
        int t = k / A_NUM;
        int jj = t % c;
        int ii = t / c;
        float sxf = (float)(jj * 16);
        float syf = (float)(ii * 16);
        float x1 = sxf + c_base[a * 4 + 0];
        float y1 = syf + c_base[a * 4 + 1];
        float x2 = sxf + c_base[a * 4 + 2];
        float y2 = syf + c_base[a * 4 + 3];
        if (!((x1 >= 0.f) && (y1 >= 0.f) && (x2 < w) && (y2 < h))) continue;

        float cx1 = fminf(fmaxf(x1, 0.f), wm1);
        float cy1 = fminf(fmaxf(y1, 0.f), hm1);
        float cx2 = fminf(fmaxf(x2, 0.f), wm1);
        float cy2 = fminf(fmaxf(y2, 0.f), hm1);

        float areaA = (cx2 - cx1 + 1.f) * (cy2 - cy1 + 1.f);
        float iw = (fminf(cx2, b.z) - fmaxf(cx1, b.x)) + 1.f;
        float ih = (fminf(cy2, b.w) - fmaxf(cy1, b.y)) + 1.f;
        float inter = fmaxf(iw, 0.f) * fmaxf(ih, 0.f);
        float denom = (areaA + areaB) - inter;
        // ascending k + strict '>' keeps the first max within a thread
        if (inter * bd > bi * denom) { bi = inter; bd = denom; bk = k; }
    }

    const unsigned FULL = 0xffffffffu;
    for (int off = 16; off; off >>= 1) {
        float oi = __shfl_down_sync(FULL, bi, off);
        float od = __shfl_down_sync(FULL, bd, off);
        int   ok = __shfl_down_sync(FULL, bk, off);
        float p1 = oi * bd, p2 = bi * od;
        if (p1 > p2 || (p1 == p2 && ok < bk)) { bi = oi; bd = od; bk = ok; }
    }

    __shared__ float si[32], sd[32];
    __shared__ int   sk[32];
    int warp = threadIdx.x >> 5, lane = threadIdx.x & 31;
    if (lane == 0) { si[warp] = bi; sd[warp] = bd; sk[warp] = bk; }
    __syncthreads();
    if (warp == 0) {
        int nw = blockDim.x >> 5;
        bi = (lane < nw) ? si[lane] : -1.f;
        bd = (lane < nw) ? sd[lane] : 1.f;
        bk = (lane < nw) ? sk[lane] : 0x7fffffff;
        for (int off = 16; off; off >>= 1) {
            float oi = __shfl_down_sync(FULL, bi, off);
            float od = __shfl_down_sync(FULL, bd, off);
            int   ok = __shfl_down_sync(FULL, bk, off);
            float p1 = oi * bd, p2 = bi * od;
            if (p1 > p2 || (p1 == p2 && ok < bk)) { bi = oi; bd = od; bk = ok; }
        }
        if (lane == 0 && bk < K) out[(size_t)8 * K + bk] = 1.0f;
    }
}

// ---------------------------------------------------------------------------
// K3: per-block pos/neg counts
// ---------------------------------------------------------------------------
__global__ void k_count(const float* __restrict__ out, int K) {
    int k = blockIdx.x * 256 + threadIdx.x;
    float l = (k < K) ? out[(size_t)8 * K + k] : -1.f;
    unsigned bp = __ballot_sync(0xffffffffu, l == 1.f);
    unsigned bn = __ballot_sync(0xffffffffu, l == 0.f);
    __shared__ int sp[8], sn[8];
    int warp = threadIdx.x >> 5, lane = threadIdx.x & 31;
    if (lane == 0) { sp[warp] = __popc(bp); sn[warp] = __popc(bn); }
    __syncthreads();
    if (threadIdx.x == 0) {
        int p = 0, n = 0;
        #pragma unroll
        for (int w2 = 0; w2 < 8; w2++) { p += sp[w2]; n += sn[w2]; }
        g_bp[blockIdx.x] = p;
        g_bn[blockIdx.x] = n;
    }
}

// ---------------------------------------------------------------------------
// K4: single-block scan of block counts; computes num_bg
// ---------------------------------------------------------------------------
__global__ void k_scan(int nb) {
    __shared__ int sp[1024], sn[1024];
    int tid = threadIdx.x;
    int vp = (tid < nb) ? g_bp[tid] : 0;
    int vn = (tid < nb) ? g_bn[tid] : 0;
    sp[tid] = vp; sn[tid] = vn;
    __syncthreads();
    for (int off = 1; off < 1024; off <<= 1) {
        int tp = (tid >= off) ? sp[tid - off] : 0;
        int tn = (tid >= off) ? sn[tid - off] : 0;
        __syncthreads();
        sp[tid] += tp; sn[tid] += tn;
        __syncthreads();
    }
    if (tid < nb) { g_pp[tid] = sp[tid] - vp; g_np[tid] = sn[tid] - vn; }
    if (tid == 0) {
        int totalPos = sp[1023];
        int numPos = totalPos < NUM_FG ? totalPos : NUM_FG;
        g_params[0] = RPN_BATCH_C - numPos;   // num_bg
    }
}

// ---------------------------------------------------------------------------
// K5: apply subsampling using global ranks
// ---------------------------------------------------------------------------
__global__ void k_apply(float* __restrict__ out, int K) {
    int b = blockIdx.x;
    int k = b * 256 + threadIdx.x;
    float* lab = out + (size_t)8 * K;
    float l = (k < K) ? lab[k] : -1.f;
    int pos = (l == 1.f);
    int neg = (l == 0.f);
    unsigned ballp = __ballot_sync(0xffffffffu, pos);
    unsigned balln = __ballot_sync(0xffffffffu, neg);
    __shared__ int sp[8], sn[8];
    int warp = threadIdx.x >> 5, lane = threadIdx.x & 31;
    if (lane == 0) { sp[warp] = __popc(ballp); sn[warp] = __popc(balln); }
    __syncthreads();
    int wp = 0, wn = 0;
    for (int w2 = 0; w2 < warp; w2++) { wp += sp[w2]; wn += sn[w2]; }
    unsigned lmask = (1u << lane) - 1u;
    int rp = g_pp[b] + wp + __popc(ballp & lmask) + 1;   // inclusive rank
    int rn = g_np[b] + wn + __popc(balln & lmask) + 1;
    int numBg = g_params[0];
    if (k < K) {
        if (pos && rp > NUM_FG) lab[k] = -1.f;
        if (neg && rn > numBg)  lab[k] = -1.f;
    }
}

// ---------------------------------------------------------------------------
extern "C" void kernel_launch(void* const* d_in, const int* in_sizes, int n_in,
                              void* d_out, int out_size) {
    const float* gt   = (const float*)d_in[0];
    const float* meta = (const float*)d_in[1];
    float* out = (float*)d_out;

    int G = in_sizes[0] / 4;
    if (G > MAX_G) G = MAX_G;
    int K = in_sizes[2];                 // r*c*A
    int rc = K / A_NUM;
    int c  = (int)(sqrt((double)rc) + 0.5);
    int nb = (K + 255) / 256;

    k_main <<<nb, 256>>>(gt, meta, out, K, c, G);
    k_col  <<<G, 1024>>>(gt, meta, out, K, c);
    k_count<<<nb, 256>>>(out, K);
    k_scan <<<1, 1024>>>(nb);
    k_apply<<<nb, 256>>>(out, K);
}

// round 4
// speedup vs baseline: 3.2445x; 3.2445x over previous
#include <cuda_runtime.h>
#include <math.h>

#define A_NUM 15
#define NUM_FG 128
#define RPN_BATCH_C 256
#define MAX_G 512
#define MAX_BLOCKS 1024

// Precomputed base anchors (BASE_SIZE=16, ratios {0.5,1,2}, scales {1,2,4,8,16})
__constant__ float c_base[60] = {
    -3.5f,   2.f,  18.5f,  13.f,
   -15.f,   -4.f,  30.f,   19.f,
   -38.f,  -16.f,  53.f,   31.f,
   -84.f,  -40.f,  99.f,   55.f,
  -176.f,  -88.f, 191.f,  103.f,
     0.f,    0.f,  15.f,   15.f,
    -8.f,   -8.f,  23.f,   23.f,
   -24.f,  -24.f,  39.f,   39.f,
   -56.f,  -56.f,  71.f,   71.f,
  -120.f, -120.f, 135.f,  135.f,
     2.5f,  -3.f,  12.5f,  18.f,
    -3.f,  -14.f,  18.f,   29.f,
   -14.f,  -36.f,  29.f,   51.f,
   -36.f,  -80.f,  51.f,   95.f,
   -80.f, -168.f,  95.f,  183.f
};

__device__ int g_bp[MAX_BLOCKS];
__device__ int g_bn[MAX_BLOCKS];
__device__ unsigned g_bar_count = 0;
__device__ volatile unsigned g_bar_gen = 0;

// Software grid barrier. Safe: grid == #SMs, 1 co-resident block per SM.
__device__ __forceinline__ void grid_barrier(int nblocks) {
    __syncthreads();
    if (threadIdx.x == 0) {
        __threadfence();
        unsigned gen = g_bar_gen;
        if (atomicAdd(&g_bar_count, 1u) == (unsigned)(nblocks - 1)) {
            atomicExch(&g_bar_count, 0u);
            __threadfence();
            g_bar_gen = gen + 1;
        } else {
            while (g_bar_gen == gen) { }
        }
        __threadfence();
    }
    __syncthreads();
}

__global__ void __launch_bounds__(1024, 1)
k_fused(const float* __restrict__ gt, const float* __restrict__ meta,
        float* __restrict__ out, int K, int r, int c, int G,
        int nblocks, int chunk) {
    __shared__ float4 s_gt[MAX_G];
    __shared__ float  s_area[MAX_G];
    __shared__ int    s_wp[32], s_wn[32];
    __shared__ float  s_ri[32], s_rd[32];
    __shared__ int    s_rk[32];
    __shared__ int    s_sc[4];

    const int tid  = threadIdx.x;
    const int bid  = blockIdx.x;
    const int lane = tid & 31;
    const int warp = tid >> 5;
    const unsigned FULL = 0xffffffffu;

    for (int g = tid; g < G; g += blockDim.x) {
        float4 b = reinterpret_cast<const float4*>(gt)[g];
        s_gt[g] = b;
        s_area[g] = (b.z - b.x + 1.0f) * (b.w - b.y + 1.0f);
    }
    __syncthreads();

    const float h = meta[0], w = meta[1];
    const float wm1 = w - 1.f, hm1 = h - 1.f;
    float*  lab = out + (size_t)8 * K;
    float4* tgt = reinterpret_cast<float4*>(out + (size_t)4 * K);

    const int base = bid * chunk;
    const int end  = min(base + chunk, K);

    // ---------------- Phase 1: per-anchor labels / targets / anchors ------
    for (int k = base + tid; k < end; k += blockDim.x) {
        int a = k % A_NUM;
        int t = k / A_NUM;
        int j = t % c;
        int i = t / c;
        float sxf = (float)(j * 16);
        float syf = (float)(i * 16);
        float x1 = sxf + c_base[a * 4 + 0];
        float y1 = syf + c_base[a * 4 + 1];
        float x2 = sxf + c_base[a * 4 + 2];
        float y2 = syf + c_base[a * 4 + 3];

        reinterpret_cast<float4*>(out)[k] = make_float4(x1, y1, x2, y2);

        bool inside = (x1 >= 0.f) && (y1 >= 0.f) && (x2 < w) && (y2 < h);
        if (!inside) {
            tgt[k] = make_float4(0.f, 0.f, 0.f, 0.f);
            lab[k] = -1.f;
            continue;
        }

        float cx1 = fminf(fmaxf(x1, 0.f), wm1);
        float cy1 = fminf(fmaxf(y1, 0.f), hm1);
        float cx2 = fminf(fmaxf(x2, 0.f), wm1);
        float cy2 = fminf(fmaxf(y2, 0.f), hm1);
        float areaA = (cx2 - cx1 + 1.f) * (cy2 - cy1 + 1.f);

        float bi = -1.f, bd = 1.f;
        int   bg = 0;
        #pragma unroll 4
        for (int g = 0; g < G; g++) {
            float4 b = s_gt[g];
            float iw = (fminf(cx2, b.z) - fmaxf(cx1, b.x)) + 1.f;
            float ih = (fminf(cy2, b.w) - fmaxf(cy1, b.y)) + 1.f;
            float inter = fmaxf(iw, 0.f) * fmaxf(ih, 0.f);
            float denom = (areaA + s_area[g]) - inter;
            if (inter * bd > bi * denom) { bi = inter; bd = denom; bg = g; }
        }

        float mo = __fdiv_rn(bi, bd);
        float l = -1.f;
        if (mo < 0.3f)  l = 0.f;
        if (mo >= 0.7f) l = 1.f;
        lab[k] = l;

        float4 gb = s_gt[bg];
        float ew = cx2 - cx1 + 1.f, eh = cy2 - cy1 + 1.f;
        float ecx = cx1 + 0.5f * ew, ecy = cy1 + 0.5f * eh;
        float gw = gb.z - gb.x + 1.f, gh = gb.w - gb.y + 1.f;
        float gcx = gb.x + 0.5f * gw, gcy = gb.y + 0.5f * gh;
        tgt[k] = make_float4(__fdiv_rn(gcx - ecx, ew),
                             __fdiv_rn(gcy - ecy, eh),
                             logf(__fdiv_rn(gw, ew)),
                             logf(__fdiv_rn(gh, eh)));
    }

    grid_barrier(nblocks);

    // ---------------- Phase 2: windowed per-gt argmax (blocks 0..G-1) -----
    if (bid < G) {
        float4 b = s_gt[bid];
        float areaB = s_area[bid];

        // Any anchor with inter>0 has its shift sx in [gx1-192, gx2+177]
        // (max base extents are -176 / +191). +1 cell safety margin.
        int j0 = max(0,     (int)floorf((b.x - 192.f) * 0.0625f) - 1);
        int j1 = min(c - 1, (int)ceilf ((b.z + 177.f) * 0.0625f) + 1);
        int i0 = max(0,     (int)floorf((b.y - 192.f) * 0.0625f) - 1);
        int i1 = min(r - 1, (int)ceilf ((b.w + 177.f) * 0.0625f) + 1);
        int nj = j1 - j0 + 1;
        int ncells = nj * (i1 - i0 + 1);
        int total = ncells * A_NUM;

        float bi = -1.f, bd = 1.f;
        int   bk = 0;

        for (int t = tid; t < total; t += blockDim.x) {
            int a    = t % A_NUM;
            int cell = t / A_NUM;
            int jj   = j0 + cell % nj;
            int ii   = i0 + cell / nj;
            float sxf = (float)(jj * 16);
            float syf = (float)(ii * 16);
            float x1 = sxf + c_base[a * 4 + 0];
            float y1 = syf + c_base[a * 4 + 1];
            float x2 = sxf + c_base[a * 4 + 2];
            float y2 = syf + c_base[a * 4 + 3];
            if (!((x1 >= 0.f) && (y1 >= 0.f) && (x2 < w) && (y2 < h))) continue;

            // inside anchors are unclipped == clipped
            float areaA = (x2 - x1 + 1.f) * (y2 - y1 + 1.f);
            float iw = (fminf(x2, b.z) - fmaxf(x1, b.x)) + 1.f;
            float ih = (fminf(y2, b.w) - fmaxf(y1, b.y)) + 1.f;
            float inter = fmaxf(iw, 0.f) * fmaxf(ih, 0.f);
            float denom = (areaA + areaB) - inter;
            int k = (ii * c + jj) * A_NUM + a;
            float p1 = inter * bd, p2 = bi * denom;
            if (p1 > p2 || (p1 == p2 && k < bk)) { bi = inter; bd = denom; bk = k; }
        }

        for (int off = 16; off; off >>= 1) {
            float oi = __shfl_down_sync(FULL, bi, off);
            float od = __shfl_down_sync(FULL, bd, off);
            int   ok = __shfl_down_sync(FULL, bk, off);
            float p1 = oi * bd, p2 = bi * od;
            if (p1 > p2 || (p1 == p2 && ok < bk)) { bi = oi; bd = od; bk = ok; }
        }
        if (lane == 0) { s_ri[warp] = bi; s_rd[warp] = bd; s_rk[warp] = bk; }
        __syncthreads();
        if (warp == 0) {
            bi = (lane < 32) ? s_ri[lane] : -1.f;
            bd = (lane < 32) ? s_rd[lane] : 1.f;
            bk = (lane < 32) ? s_rk[lane] : 0x7fffffff;
            for (int off = 16; off; off >>= 1) {
                float oi = __shfl_down_sync(FULL, bi, off);
                float od = __shfl_down_sync(FULL, bd, off);
                int   ok = __shfl_down_sync(FULL, bk, off);
                float p1 = oi * bd, p2 = bi * od;
                if (p1 > p2 || (p1 == p2 && ok < bk)) { bi = oi; bd = od; bk = ok; }
            }
            if (lane == 0 && bk < K) lab[bk] = 1.0f;
        }
    }

    grid_barrier(nblocks);

    // ---------------- Phase 3a: per-block pos/neg counts ------------------
    int cp = 0, cn = 0;
    for (int k = base + tid; k < end; k += blockDim.x) {
        float l = __ldcg(&lab[k]);          // bypass L1: other SMs wrote labels
        cp += (l == 1.f);
        cn += (l == 0.f);
    }
    for (int off = 16; off; off >>= 1) {
        cp += __shfl_down_sync(FULL, cp, off);
        cn += __shfl_down_sync(FULL, cn, off);
    }
    if (lane == 0) { s_wp[warp] = cp; s_wn[warp] = cn; }
    __syncthreads();
    if (tid == 0) {
        int p = 0, n = 0;
        #pragma unroll
        for (int v = 0; v < 32; v++) { p += s_wp[v]; n += s_wn[v]; }
        g_bp[bid] = p; g_bn[bid] = n;
    }

    grid_barrier(nblocks);

    // ---------------- Phase 3b: prefix + apply ----------------------------
    if (tid == 0) {
        int pp = 0, np = 0, tp = 0;
        for (int t = 0; t < nblocks; t++) {
            int p = __ldcg(&g_bp[t]);
            int n = __ldcg(&g_bn[t]);
            if (t < bid) { pp += p; np += n; }
            tp += p;
        }
        int numPos = tp < NUM_FG ? tp : NUM_FG;
        s_sc[0] = pp; s_sc[1] = np; s_sc[2] = RPN_BATCH_C - numPos;
    }
    __syncthreads();
    int runP = s_sc[0], runN = s_sc[1];
    const int numBg = s_sc[2];

    for (int s = base; s < end; s += blockDim.x) {
        int k = s + tid;
        float l = (k < end) ? __ldcg(&lab[k]) : -1.f;
        int pos = (l == 1.f);
        int neg = (l == 0.f);
        unsigned ballp = __ballot_sync(FULL, pos);
        unsigned balln = __ballot_sync(FULL, neg);
        if (lane == 0) { s_wp[warp] = __popc(ballp); s_wn[warp] = __popc(balln); }
        __syncthreads();
        int wp = 0, wn = 0, totP = 0, totN = 0;
        #pragma unroll
        for (int v = 0; v < 32; v++) {
            int a = s_wp[v], b2 = s_wn[v];
            if (v < warp) { wp += a; wn += b2; }
            totP += a; totN += b2;
        }
        unsigned lm = (1u << lane) - 1u;
        int rp = runP + wp + __popc(ballp & lm) + 1;
        int rn = runN + wn + __popc(balln & lm) + 1;
        if (k < end) {
            if (pos && rp > NUM_FG) lab[k] = -1.f;
            if (neg && rn > numBg)  lab[k] = -1.f;
        }
        runP += totP; runN += totN;
        __syncthreads();
    }
}

// ---------------------------------------------------------------------------
extern "C" void kernel_launch(void* const* d_in, const int* in_sizes, int n_in,
                              void* d_out, int out_size) {
    const float* gt   = (const float*)d_in[0];
    const float* meta = (const float*)d_in[1];
    float* out = (float*)d_out;

    int G = in_sizes[0] / 4;
    if (G > MAX_G) G = MAX_G;
    int K  = in_sizes[2];
    int rc = K / A_NUM;
    int c  = (int)(sqrt((double)rc) + 0.5);
    int r  = rc / c;

    int dev = 0;
    cudaGetDevice(&dev);
    int nsm = 0;
    cudaDeviceGetAttribute(&nsm, cudaDevAttrMultiProcessorCount, dev);
    if (nsm <= 0) nsm = 148;
    int nblocks = nsm < MAX_BLOCKS ? nsm : MAX_BLOCKS;
    int chunk = (K + nblocks - 1) / nblocks;

    k_fused<<<nblocks, 1024>>>(gt, meta, out, K, r, c, G, nblocks, chunk);
}

// round 5
// speedup vs baseline: 3.9802x; 1.2268x over previous
#include <cuda_runtime.h>
#include <math.h>

#define A_NUM 15
#define NUM_FG 128
#define RPN_BATCH_C 256
#define MAX_G 512
#define MAX_BLOCKS 256

// Precomputed base anchors (BASE_SIZE=16, ratios {0.5,1,2}, scales {1,2,4,8,16})
__constant__ float c_base[60] = {
    -3.5f,   2.f,  18.5f,  13.f,
   -15.f,   -4.f,  30.f,   19.f,
   -38.f,  -16.f,  53.f,   31.f,
   -84.f,  -40.f,  99.f,   55.f,
  -176.f,  -88.f, 191.f,  103.f,
     0.f,    0.f,  15.f,   15.f,
    -8.f,   -8.f,  23.f,   23.f,
   -24.f,  -24.f,  39.f,   39.f,
   -56.f,  -56.f,  71.f,   71.f,
  -120.f, -120.f, 135.f,  135.f,
     2.5f,  -3.f,  12.5f,  18.f,
    -3.f,  -14.f,  18.f,   29.f,
   -14.f,  -36.f,  29.f,   51.f,
   -36.f,  -80.f,  51.f,   95.f,
   -80.f, -168.f,  95.f,  183.f
};

__device__ int g_bp[MAX_BLOCKS];
__device__ int g_bn[MAX_BLOCKS];
__device__ unsigned g_bar_count = 0;
__device__ volatile unsigned g_bar_gen = 0;

// Software grid barrier. Safe: grid == #SMs, 1 co-resident block per SM.
__device__ __forceinline__ void grid_barrier(int nblocks) {
    __syncthreads();
    if (threadIdx.x == 0) {
        __threadfence();
        unsigned gen = g_bar_gen;
        if (atomicAdd(&g_bar_count, 1u) == (unsigned)(nblocks - 1)) {
            atomicExch(&g_bar_count, 0u);
            __threadfence();
            g_bar_gen = gen + 1;
        } else {
            while (g_bar_gen == gen) { }
        }
        __threadfence();
    }
    __syncthreads();
}

__global__ void __launch_bounds__(1024, 1)
k_fused(const float* __restrict__ gt, const float* __restrict__ meta,
        float* __restrict__ out, int K, int r, int c, int G,
        int nblocks, int chunk) {
    __shared__ float4 s_gt[MAX_G];
    __shared__ float  s_area[MAX_G];
    __shared__ float4 s_cg[MAX_G];       // y-pruned candidate boxes (ordered)
    __shared__ float  s_ca[MAX_G];       // their areas
    __shared__ int    s_ncand;
    __shared__ int    s_wp[32], s_wn[32];
    __shared__ float  s_ri[32], s_rd[32];
    __shared__ int    s_rk[32];
    __shared__ int    s_sp[MAX_BLOCKS], s_sn[MAX_BLOCKS];

    const int tid  = threadIdx.x;
    const int bid  = blockIdx.x;
    const int lane = tid & 31;
    const int warp = tid >> 5;
    const unsigned FULL = 0xffffffffu;

    for (int g = tid; g < G; g += blockDim.x) {
        float4 b = reinterpret_cast<const float4*>(gt)[g];
        s_gt[g] = b;
        s_area[g] = (b.z - b.x + 1.0f) * (b.w - b.y + 1.0f);
    }
    __syncthreads();

    const float h = meta[0], w = meta[1];
    const float wm1 = w - 1.f, hm1 = h - 1.f;
    float*  lab = out + (size_t)8 * K;
    float4* tgt = reinterpret_cast<float4*>(out + (size_t)4 * K);

    const int base = bid * chunk;
    const int end  = min(base + chunk, K);

    // ---- build y-pruned candidate gt list for this block's chunk ---------
    {
        int t0 = base / A_NUM;
        int t1 = (end - 1) / A_NUM;
        float ymin = (float)((t0 / c) * 16) - 194.f;   // conservative window
        float ymax = (float)((t1 / c) * 16) + 194.f;
        if (warp == 0) {
            int cnt = 0;
            for (int gb = 0; gb < G; gb += 32) {
                int g = gb + lane;
                bool ok = false;
                float4 b;
                float ar = 0.f;
                if (g < G) {
                    b = s_gt[g]; ar = s_area[g];
                    ok = (b.y <= ymax) && (b.w >= ymin);
                }
                unsigned m = __ballot_sync(FULL, ok);
                int pos = cnt + __popc(m & ((1u << lane) - 1u));
                if (ok) { s_cg[pos] = b; s_ca[pos] = ar; }
                cnt += __popc(m);
            }
            if (lane == 0) s_ncand = cnt;
        }
    }
    __syncthreads();
    const int ncand = s_ncand;
    const float4 gb0 = s_gt[0];

    // ---------------- Phase 1: per-anchor labels / targets / anchors ------
    for (int k = base + tid; k < end; k += blockDim.x) {
        int a = k % A_NUM;
        int t = k / A_NUM;
        int j = t % c;
        int i = t / c;
        float sxf = (float)(j * 16);
        float syf = (float)(i * 16);
        float x1 = sxf + c_base[a * 4 + 0];
        float y1 = syf + c_base[a * 4 + 1];
        float x2 = sxf + c_base[a * 4 + 2];
        float y2 = syf + c_base[a * 4 + 3];

        reinterpret_cast<float4*>(out)[k] = make_float4(x1, y1, x2, y2);

        bool inside = (x1 >= 0.f) && (y1 >= 0.f) && (x2 < w) && (y2 < h);
        if (!inside) {
            tgt[k] = make_float4(0.f, 0.f, 0.f, 0.f);
            lab[k] = -1.f;
            continue;
        }

        float cx1 = fminf(fmaxf(x1, 0.f), wm1);
        float cy1 = fminf(fmaxf(y1, 0.f), hm1);
        float cx2 = fminf(fmaxf(x2, 0.f), wm1);
        float cy2 = fminf(fmaxf(y2, 0.f), hm1);
        float areaA = (cx2 - cx1 + 1.f) * (cy2 - cy1 + 1.f);

        // bi=0 baseline == "gt[0] at IoU 0" (argmax of all-zero row is 0)
        float bi = 0.f, bd = 1.f;
        int   bg = -1;
        for (int g = 0; g < ncand; g++) {
            float4 b = s_cg[g];
            float iw = (fminf(cx2, b.z) - fmaxf(cx1, b.x)) + 1.f;
            float ih = (fminf(cy2, b.w) - fmaxf(cy1, b.y)) + 1.f;
            if (iw > 0.f && ih > 0.f) {
                float inter = iw * ih;
                float denom = (areaA + s_ca[g]) - inter;
                if (inter * bd > bi * denom) { bi = inter; bd = denom; bg = g; }
            }
        }

        float mo = __fdiv_rn(bi, bd);
        float l = -1.f;
        if (mo < 0.3f)  l = 0.f;
        if (mo >= 0.7f) l = 1.f;
        lab[k] = l;

        float4 gb = (bg >= 0) ? s_cg[bg] : gb0;
        float ew = cx2 - cx1 + 1.f, eh = cy2 - cy1 + 1.f;
        float ecx = cx1 + 0.5f * ew, ecy = cy1 + 0.5f * eh;
        float gw = gb.z - gb.x + 1.f, gh = gb.w - gb.y + 1.f;
        float gcx = gb.x + 0.5f * gw, gcy = gb.y + 0.5f * gh;
        tgt[k] = make_float4(__fdiv_rn(gcx - ecx, ew),
                             __fdiv_rn(gcy - ecy, eh),
                             logf(__fdiv_rn(gw, ew)),
                             logf(__fdiv_rn(gh, eh)));
    }

    grid_barrier(nblocks);

    // ---------------- Phase 2: windowed per-gt argmax (blocks 0..G-1) -----
    if (bid < G) {
        float4 b = s_gt[bid];
        float areaB = s_area[bid];

        int j0 = max(0,     (int)floorf((b.x - 192.f) * 0.0625f) - 1);
        int j1 = min(c - 1, (int)ceilf ((b.z + 177.f) * 0.0625f) + 1);
        int i0 = max(0,     (int)floorf((b.y - 192.f) * 0.0625f) - 1);
        int i1 = min(r - 1, (int)ceilf ((b.w + 177.f) * 0.0625f) + 1);
        int nj = j1 - j0 + 1;
        int ncells = nj * (i1 - i0 + 1);
        int total = ncells * A_NUM;

        float bi = -1.f, bd = 1.f;
        int   bk = 0;

        for (int t = tid; t < total; t += blockDim.x) {
            int a    = t % A_NUM;
            int cell = t / A_NUM;
            int jj   = j0 + cell % nj;
            int ii   = i0 + cell / nj;
            float sxf = (float)(jj * 16);
            float syf = (float)(ii * 16);
            float x1 = sxf + c_base[a * 4 + 0];
            float y1 = syf + c_base[a * 4 + 1];
            float x2 = sxf + c_base[a * 4 + 2];
            float y2 = syf + c_base[a * 4 + 3];
            if (!((x1 >= 0.f) && (y1 >= 0.f) && (x2 < w) && (y2 < h))) continue;

            float areaA = (x2 - x1 + 1.f) * (y2 - y1 + 1.f);
            float iw = (fminf(x2, b.z) - fmaxf(x1, b.x)) + 1.f;
            float ih = (fminf(y2, b.w) - fmaxf(y1, b.y)) + 1.f;
            float inter = fmaxf(iw, 0.f) * fmaxf(ih, 0.f);
            float denom = (areaA + areaB) - inter;
            int k = (ii * c + jj) * A_NUM + a;
            float p1 = inter * bd, p2 = bi * denom;
            if (p1 > p2 || (p1 == p2 && k < bk)) { bi = inter; bd = denom; bk = k; }
        }

        for (int off = 16; off; off >>= 1) {
            float oi = __shfl_down_sync(FULL, bi, off);
            float od = __shfl_down_sync(FULL, bd, off);
            int   ok = __shfl_down_sync(FULL, bk, off);
            float p1 = oi * bd, p2 = bi * od;
            if (p1 > p2 || (p1 == p2 && ok < bk)) { bi = oi; bd = od; bk = ok; }
        }
        if (lane == 0) { s_ri[warp] = bi; s_rd[warp] = bd; s_rk[warp] = bk; }
        __syncthreads();
        if (warp == 0) {
            bi = s_ri[lane];
            bd = s_rd[lane];
            bk = s_rk[lane];
            for (int off = 16; off; off >>= 1) {
                float oi = __shfl_down_sync(FULL, bi, off);
                float od = __shfl_down_sync(FULL, bd, off);
                int   ok = __shfl_down_sync(FULL, bk, off);
                float p1 = oi * bd, p2 = bi * od;
                if (p1 > p2 || (p1 == p2 && ok < bk)) { bi = oi; bd = od; bk = ok; }
            }
            if (lane == 0 && bk < K) lab[bk] = 1.0f;
        }
    }

    grid_barrier(nblocks);

    // ---------------- Phase 3a: per-block pos/neg counts ------------------
    int cp = 0, cn = 0;
    for (int k = base + tid; k < end; k += blockDim.x) {
        float l = __ldcg(&lab[k]);          // bypass L1: other SMs wrote labels
        cp += (l == 1.f);
        cn += (l == 0.f);
    }
    for (int off = 16; off; off >>= 1) {
        cp += __shfl_down_sync(FULL, cp, off);
        cn += __shfl_down_sync(FULL, cn, off);
    }
    if (lane == 0) { s_wp[warp] = cp; s_wn[warp] = cn; }
    __syncthreads();
    if (tid == 0) {
        int p = 0, n = 0;
        #pragma unroll
        for (int v = 0; v < 32; v++) { p += s_wp[v]; n += s_wn[v]; }
        g_bp[bid] = p; g_bn[bid] = n;
    }

    grid_barrier(nblocks);

    // ---------------- Phase 3b: parallel prefix + apply -------------------
    if (tid < MAX_BLOCKS) {
        s_sp[tid] = (tid < nblocks) ? __ldcg(&g_bp[tid]) : 0;
        s_sn[tid] = (tid < nblocks) ? __ldcg(&g_bn[tid]) : 0;
    }
    __syncthreads();
    for (int off = 1; off < MAX_BLOCKS; off <<= 1) {
        int tp = 0, tn = 0;
        if (tid < MAX_BLOCKS && tid >= off) { tp = s_sp[tid - off]; tn = s_sn[tid - off]; }
        __syncthreads();
        if (tid < MAX_BLOCKS) { s_sp[tid] += tp; s_sn[tid] += tn; }
        __syncthreads();
    }
    int runP = (bid > 0) ? s_sp[bid - 1] : 0;
    int runN = (bid > 0) ? s_sn[bid - 1] : 0;
    int totP = s_sp[MAX_BLOCKS - 1];
    const int numBg = RPN_BATCH_C - (totP < NUM_FG ? totP : NUM_FG);
    __syncthreads();

    for (int s = base; s < end; s += blockDim.x) {
        int k = s + tid;
        float l = (k < end) ? __ldcg(&lab[k]) : -1.f;
        int pos = (l == 1.f);
        int neg = (l == 0.f);
        unsigned ballp = __ballot_sync(FULL, pos);
        unsigned balln = __ballot_sync(FULL, neg);
        if (lane == 0) { s_wp[warp] = __popc(ballp); s_wn[warp] = __popc(balln); }
        __syncthreads();
        int wp = 0, wn = 0, totPb = 0, totNb = 0;
        #pragma unroll
        for (int v = 0; v < 32; v++) {
            int a2 = s_wp[v], b2 = s_wn[v];
            if (v < warp) { wp += a2; wn += b2; }
            totPb += a2; totNb += b2;
        }
        unsigned lm = (1u << lane) - 1u;
        int rp = runP + wp + __popc(ballp & lm) + 1;
        int rn = runN + wn + __popc(balln & lm) + 1;
        if (k < end) {
            if (pos && rp > NUM_FG) lab[k] = -1.f;
            if (neg && rn > numBg)  lab[k] = -1.f;
        }
        runP += totPb; runN += totNb;
        __syncthreads();
    }
}

// ---------------------------------------------------------------------------
extern "C" void kernel_launch(void* const* d_in, const int* in_sizes, int n_in,
                              void* d_out, int out_size) {
    const float* gt   = (const float*)d_in[0];
    const float* meta = (const float*)d_in[1];
    float* out = (float*)d_out;

    int G = in_sizes[0] / 4;
    if (G > MAX_G) G = MAX_G;
    int K  = in_sizes[2];
    int rc = K / A_NUM;
    int c  = (int)(sqrt((double)rc) + 0.5);
    int r  = rc / c;

    int dev = 0;
    cudaGetDevice(&dev);
    int nsm = 0;
    cudaDeviceGetAttribute(&nsm, cudaDevAttrMultiProcessorCount, dev);
    if (nsm <= 0) nsm = 148;
    int nblocks = nsm < MAX_BLOCKS ? nsm : MAX_BLOCKS;
    int chunk = (K + nblocks - 1) / nblocks;

    k_fused<<<nblocks, 1024>>>(gt, meta, out, K, r, c, G, nblocks, chunk);
}

// round 7
// speedup vs baseline: 7.4842x; 1.8803x over previous
#include <cuda_runtime.h>
#include <math.h>

#define A_NUM 15
#define NUM_FG 128
#define RPN_BATCH_C 256
#define MAX_G 512
#define MAX_P1 512
#define TPB 512
#define NW (TPB / 32)
#define WCAP 160

// Base anchors as compile-time constants (folded to immediates in unrolled code)
__device__ constexpr float BAX1[15] = {-3.5f,-15.f,-38.f,-84.f,-176.f,  0.f, -8.f,-24.f,-56.f,-120.f,  2.5f, -3.f,-14.f,-36.f,-80.f};
__device__ constexpr float BAY1[15] = {  2.f, -4.f,-16.f,-40.f, -88.f,  0.f, -8.f,-24.f,-56.f,-120.f, -3.f,-14.f,-36.f,-80.f,-168.f};
__device__ constexpr float BAX2[15] = { 18.5f, 30.f, 53.f, 99.f, 191.f, 15.f, 23.f, 39.f, 71.f, 135.f, 12.5f, 18.f, 29.f, 51.f, 95.f};
__device__ constexpr float BAY2[15] = { 13.f, 19.f, 31.f, 55.f, 103.f, 15.f, 23.f, 39.f, 71.f, 135.f, 18.f, 29.f, 51.f, 95.f, 183.f};
__device__ constexpr float BAREA[15] = {276.f,1104.f,4416.f,17664.f,70656.f, 256.f,1024.f,4096.f,16384.f,65536.f, 242.f,968.f,3872.f,15488.f,61952.f};

// Same table in constant memory for runtime-indexed access (phase 1)
__constant__ float c_base[60] = {
    -3.5f,   2.f,  18.5f,  13.f,   -15.f,   -4.f,  30.f,   19.f,
   -38.f,  -16.f,  53.f,   31.f,   -84.f,  -40.f,  99.f,   55.f,
  -176.f,  -88.f, 191.f,  103.f,     0.f,    0.f,  15.f,   15.f,
    -8.f,   -8.f,  23.f,   23.f,   -24.f,  -24.f,  39.f,   39.f,
   -56.f,  -56.f,  71.f,   71.f,  -120.f, -120.f, 135.f,  135.f,
     2.5f,  -3.f,  12.5f,  18.f,    -3.f,  -14.f,  18.f,   29.f,
   -14.f,  -36.f,  29.f,   51.f,   -36.f,  -80.f,  51.f,   95.f,
   -80.f, -168.f,  95.f,  183.f
};

__device__ int g_bp[MAX_P1];
__device__ int g_bn[MAX_P1];
__device__ int g_win[MAX_G];
__device__ unsigned g_bar_count = 0;
__device__ volatile unsigned g_bar_gen = 0;

// Software grid barrier. Valid: all blocks co-resident (grid = 2 * #SMs, occ 2).
__device__ __forceinline__ void grid_barrier(int nblocks) {
    __syncthreads();
    if (threadIdx.x == 0) {
        __threadfence();
        unsigned gen = g_bar_gen;
        if (atomicAdd(&g_bar_count, 1u) == (unsigned)(nblocks - 1)) {
            atomicExch(&g_bar_count, 0u);
            __threadfence();
            g_bar_gen = gen + 1;
        } else {
            while (g_bar_gen == gen) { }
        }
        __threadfence();
    }
    __syncthreads();
}

__global__ void __launch_bounds__(TPB, 2)
k_fused(const float* __restrict__ gt, const float* __restrict__ meta,
        float* __restrict__ out, int K, int r, int c, int G,
        int nblocks, int nP1, int chunk) {
    __shared__ float4 s_gt[MAX_G];
    __shared__ float  s_area[MAX_G];
    __shared__ unsigned char s_widx[NW][WCAP];
    __shared__ int    s_wp[NW], s_wn[NW];
    __shared__ float  s_ri[NW], s_rd[NW];
    __shared__ int    s_rk[NW];
    __shared__ int    s_sp[MAX_P1], s_sn[MAX_P1];

    const int tid  = threadIdx.x;
    const int bid  = blockIdx.x;
    const int lane = tid & 31;
    const int warp = tid >> 5;
    const unsigned FULL = 0xffffffffu;

    for (int g = tid; g < G; g += TPB) {
        float4 b = reinterpret_cast<const float4*>(gt)[g];
        s_gt[g] = b;
        s_area[g] = (b.z - b.x + 1.0f) * (b.w - b.y + 1.0f);
    }
    __syncthreads();

    const float h = meta[0], w = meta[1];
    const float wm1 = w - 1.f, hm1 = h - 1.f;
    float*  lab = out + (size_t)8 * K;
    float4* tgt = reinterpret_cast<float4*>(out + (size_t)4 * K);

    const bool isP1 = (bid < nP1);
    const int base = isP1 ? bid * chunk : 0;
    const int end  = isP1 ? min(base + chunk, K) : 0;
    const float4 gb0 = s_gt[0];

    if (isP1) {
        // ============ Phase 1: per-anchor labels / targets / anchors ======
        for (int sb = base; sb < end; sb += TPB) {
            int k = sb + tid;
            int kk = min(k, end - 1);
            int t2 = kk / A_NUM;
            int a  = kk - t2 * A_NUM;
            int ii = t2 / c;
            int jj = t2 - ii * c;
            float sx = (float)(jj * 16);
            float sy = (float)(ii * 16);

            // per-warp spatial window
            float sxlo = sx, sxhi = sx, sylo = sy, syhi = sy;
            #pragma unroll
            for (int off = 16; off; off >>= 1) {
                sxlo = fminf(sxlo, __shfl_xor_sync(FULL, sxlo, off));
                sxhi = fmaxf(sxhi, __shfl_xor_sync(FULL, sxhi, off));
                sylo = fminf(sylo, __shfl_xor_sync(FULL, sylo, off));
                syhi = fmaxf(syhi, __shfl_xor_sync(FULL, syhi, off));
            }
            float xlo = sxlo - 178.f, xhi = sxhi + 193.f;
            float ylo = sylo - 170.f, yhi = syhi + 185.f;

            // warp-filtered gt candidate list (ascending g)
            int cnt = 0;
            unsigned lmask = (1u << lane) - 1u;
            for (int gb = 0; gb < G; gb += 32) {
                int g = gb + lane;
                bool ok = false;
                if (g < G) {
                    float4 b = s_gt[g];
                    ok = (b.y <= yhi) && (b.w >= ylo) && (b.x <= xhi) && (b.z >= xlo);
                }
                unsigned m = __ballot_sync(FULL, ok);
                int pos = cnt + __popc(m & lmask);
                if (ok && pos < WCAP) s_widx[warp][pos] = (unsigned char)g;
                cnt += __popc(m);
            }
            if (cnt > WCAP) cnt = WCAP;
            __syncwarp(FULL);

            if (k >= end) continue;

            float x1 = sx + c_base[a * 4 + 0];
            float y1 = sy + c_base[a * 4 + 1];
            float x2 = sx + c_base[a * 4 + 2];
            float y2 = sy + c_base[a * 4 + 3];

            reinterpret_cast<float4*>(out)[k] = make_float4(x1, y1, x2, y2);

            bool inside = (x1 >= 0.f) && (y1 >= 0.f) && (x2 < w) && (y2 < h);
            if (!inside) {
                tgt[k] = make_float4(0.f, 0.f, 0.f, 0.f);
                lab[k] = -1.f;
                continue;
            }

            float cx1 = fminf(fmaxf(x1, 0.f), wm1);
            float cy1 = fminf(fmaxf(y1, 0.f), hm1);
            float cx2 = fminf(fmaxf(x2, 0.f), wm1);
            float cy2 = fminf(fmaxf(y2, 0.f), hm1);
            float areaA = (cx2 - cx1 + 1.f) * (cy2 - cy1 + 1.f);

            float bi = 0.f, bd = 1.f;     // matches "all-zero row -> argmax 0"
            int   bg = -1;
            #pragma unroll 4
            for (int t3 = 0; t3 < cnt; t3++) {
                int g = s_widx[warp][t3];
                float4 b = s_gt[g];
                float iw = (fminf(cx2, b.z) - fmaxf(cx1, b.x)) + 1.f;
                float ih = (fminf(cy2, b.w) - fmaxf(cy1, b.y)) + 1.f;
                float inter = fmaxf(iw, 0.f) * fmaxf(ih, 0.f);
                float denom = (areaA + s_area[g]) - inter;
                if (inter * bd > bi * denom) { bi = inter; bd = denom; bg = g; }
            }

            float mo = __fdiv_rn(bi, bd);   // exact: feeds label thresholds
            float l = -1.f;
            if (mo < 0.3f)  l = 0.f;
            if (mo >= 0.7f) l = 1.f;
            lab[k] = l;

            float4 gb = (bg >= 0) ? s_gt[bg] : gb0;
            float ew = cx2 - cx1 + 1.f, eh = cy2 - cy1 + 1.f;
            float ecx = cx1 + 0.5f * ew, ecy = cy1 + 0.5f * eh;
            float gw = gb.z - gb.x + 1.f, gh = gb.w - gb.y + 1.f;
            float gcx = gb.x + 0.5f * gw, gcy = gb.y + 0.5f * gh;
            tgt[k] = make_float4(__fdividef(gcx - ecx, ew),
                                 __fdividef(gcy - ecy, eh),
                                 __logf(__fdividef(gw, ew)),
                                 __logf(__fdividef(gh, eh)));
        }
    } else {
        // ============ Phase 2 (concurrent): per-gt argmax ================
        for (int g = bid - nP1; g < G; g += nblocks - nP1) {
            float4 b = s_gt[g];
            float areaB = s_area[g];

            int j0 = max(0,     (int)floorf((b.x - 193.f) * 0.0625f) - 1);
            int j1 = min(c - 1, (int)ceilf ((b.z + 178.f) * 0.0625f) + 1);
            int i0 = max(0,     (int)floorf((b.y - 185.f) * 0.0625f) - 1);
            int i1 = min(r - 1, (int)ceilf ((b.w + 170.f) * 0.0625f) + 1);
            int nj = j1 - j0 + 1;
            int ncells = nj * (i1 - i0 + 1);

            float bi = -1.f, bd = 1.f;
            int   bk = 0x7fffffff;

            for (int t = tid; t < ncells; t += TPB) {
                int dv = t / nj;
                int jj = j0 + (t - dv * nj);
                int ii = i0 + dv;
                float sx = (float)(jj * 16);
                float sy = (float)(ii * 16);
                int kbase = (ii * c + jj) * A_NUM;
                #pragma unroll
                for (int a = 0; a < A_NUM; a++) {
                    float x1 = sx + BAX1[a];
                    float y1 = sy + BAY1[a];
                    float x2 = sx + BAX2[a];
                    float y2 = sy + BAY2[a];
                    bool ins = (x1 >= 0.f) && (y1 >= 0.f) && (x2 < w) && (y2 < h);
                    float iw = (fminf(x2, b.z) - fmaxf(x1, b.x)) + 1.f;
                    float ih = (fminf(y2, b.w) - fmaxf(y1, b.y)) + 1.f;
                    float inter = fmaxf(iw, 0.f) * fmaxf(ih, 0.f);
                    float denom = (BAREA[a] + areaB) - inter;
                    int k = kbase + a;
                    float p1 = inter * bd, p2 = bi * denom;
                    if (ins && (p1 > p2 || (p1 == p2 && k < bk))) {
                        bi = inter; bd = denom; bk = k;
                    }
                }
            }

            #pragma unroll
            for (int off = 16; off; off >>= 1) {
                float oi = __shfl_down_sync(FULL, bi, off);
                float od = __shfl_down_sync(FULL, bd, off);
                int   ok = __shfl_down_sync(FULL, bk, off);
                float p1 = oi * bd, p2 = bi * od;
                if (p1 > p2 || (p1 == p2 && ok < bk)) { bi = oi; bd = od; bk = ok; }
            }
            if (lane == 0) { s_ri[warp] = bi; s_rd[warp] = bd; s_rk[warp] = bk; }
            __syncthreads();
            if (warp == 0) {
                bi = (lane < NW) ? s_ri[lane] : -1.f;
                bd = (lane < NW) ? s_rd[lane] : 1.f;
                bk = (lane < NW) ? s_rk[lane] : 0x7fffffff;
                #pragma unroll
                for (int off = 16; off; off >>= 1) {
                    float oi = __shfl_down_sync(FULL, bi, off);
                    float od = __shfl_down_sync(FULL, bd, off);
                    int   ok = __shfl_down_sync(FULL, bk, off);
                    float p1 = oi * bd, p2 = bi * od;
                    if (p1 > p2 || (p1 == p2 && ok < bk)) { bi = oi; bd = od; bk = ok; }
                }
                if (lane == 0) g_win[g] = bk;   // ordered by barrier fence
            }
            __syncthreads();
        }
    }

    grid_barrier(nblocks);

    if (isP1) {
        // ---- apply winners that fall in my chunk, then count -------------
        if (tid < G) {
            int kw = __ldcg(&g_win[tid]);
            if (kw >= base && kw < end) lab[kw] = 1.0f;
        }
        __syncthreads();

        int cp = 0, cn = 0;
        for (int k = base + tid; k < end; k += TPB) {
            float l = lab[k];               // own block wrote everything here
            cp += (l == 1.f);
            cn += (l == 0.f);
        }
        #pragma unroll
        for (int off = 16; off; off >>= 1) {
            cp += __shfl_down_sync(FULL, cp, off);
            cn += __shfl_down_sync(FULL, cn, off);
        }
        if (lane == 0) { s_wp[warp] = cp; s_wn[warp] = cn; }
        __syncthreads();
        if (tid == 0) {
            int p = 0, n = 0;
            #pragma unroll
            for (int v = 0; v < NW; v++) { p += s_wp[v]; n += s_wn[v]; }
            g_bp[bid] = p; g_bn[bid] = n;
        }
    }

    grid_barrier(nblocks);
    if (!isP1) return;

    // ---- scan block counts + apply subsampling ---------------------------
    s_sp[tid] = (tid < nP1) ? __ldcg(&g_bp[tid]) : 0;
    s_sn[tid] = (tid < nP1) ? __ldcg(&g_bn[tid]) : 0;
    __syncthreads();
    #pragma unroll
    for (int off = 1; off < MAX_P1; off <<= 1) {
        int tp = (tid >= off) ? s_sp[tid - off] : 0;
        int tn = (tid >= off) ? s_sn[tid - off] : 0;
        __syncthreads();
        s_sp[tid] += tp; s_sn[tid] += tn;
        __syncthreads();
    }
    int runP = (bid > 0) ? s_sp[bid - 1] : 0;
    int runN = (bid > 0) ? s_sn[bid - 1] : 0;
    int totP = s_sp[MAX_P1 - 1];
    const int numBg = RPN_BATCH_C - (totP < NUM_FG ? totP : NUM_FG);
    __syncthreads();

    for (int s = base; s < end; s += TPB) {
        int k = s + tid;
        float l = (k < end) ? lab[k] : -1.f;
        int pos = (l == 1.f);
        int neg = (l == 0.f);
        unsigned ballp = __ballot_sync(FULL, pos);
        unsigned balln = __ballot_sync(FULL, neg);
        if (lane == 0) { s_wp[warp] = __popc(ballp); s_wn[warp] = __popc(balln); }
        __syncthreads();
        int wp = 0, wn = 0, totPb = 0, totNb = 0;
        #pragma unroll
        for (int v = 0; v < NW; v++) {
            int a2 = s_wp[v], b2 = s_wn[v];
            if (v < warp) { wp += a2; wn += b2; }
            totPb += a2; totNb += b2;
        }
        unsigned lm = (1u << lane) - 1u;
        int rp = runP + wp + __popc(ballp & lm) + 1;
        int rn = runN + wn + __popc(balln & lm) + 1;
        if (k < end) {
            if (pos && rp > NUM_FG) lab[k] = -1.f;
            if (neg && rn > numBg)  lab[k] = -1.f;
        }
        runP += totPb; runN += totNb;
        __syncthreads();
    }
}

// ---------------------------------------------------------------------------
extern "C" void kernel_launch(void* const* d_in, const int* in_sizes, int n_in,
                              void* d_out, int out_size) {
    const float* gt   = (const float*)d_in[0];
    const float* meta = (const float*)d_in[1];
    float* out = (float*)d_out;

    int G = in_sizes[0] / 4;
    if (G > MAX_G) G = MAX_G;
    int K  = in_sizes[2];
    int rc = K / A_NUM;
    int c  = (int)(sqrt((double)rc) + 0.5);
    int r  = rc / c;

    int dev = 0;
    cudaGetDevice(&dev);
    int nsm = 0;
    cudaDeviceGetAttribute(&nsm, cudaDevAttrMultiProcessorCount, dev);
    if (nsm <= 0) nsm = 148;
    int nblocks = 2 * nsm;               // 2 co-resident blocks per SM
    int nP1 = nblocks - G;               // dedicated phase-1 blocks
    if (nP1 < nblocks / 2) nP1 = nblocks / 2;
    if (nP1 > MAX_P1) nP1 = MAX_P1;
    int chunk = (K + nP1 - 1) / nP1;

    k_fused<<<nblocks, TPB>>>(gt, meta, out, K, r, c, G, nblocks, nP1, chunk);
}

// round 9
// speedup vs baseline: 7.5675x; 1.0111x over previous
#include <cuda_runtime.h>
#include <math.h>

#define A_NUM 15
#define NUM_FG 128
#define RPN_BATCH_C 256
#define MAX_G 512
#define MAX_P1 512
#define TPB 512
#define NW (TPB / 32)

// Base anchors as compile-time constants (folded to immediates in unrolled code)
__device__ constexpr float BAX1[15] = {-3.5f,-15.f,-38.f,-84.f,-176.f,  0.f, -8.f,-24.f,-56.f,-120.f,  2.5f, -3.f,-14.f,-36.f,-80.f};
__device__ constexpr float BAY1[15] = {  2.f, -4.f,-16.f,-40.f, -88.f,  0.f, -8.f,-24.f,-56.f,-120.f, -3.f,-14.f,-36.f,-80.f,-168.f};
__device__ constexpr float BAX2[15] = { 18.5f, 30.f, 53.f, 99.f, 191.f, 15.f, 23.f, 39.f, 71.f, 135.f, 12.5f, 18.f, 29.f, 51.f, 95.f};
__device__ constexpr float BAY2[15] = { 13.f, 19.f, 31.f, 55.f, 103.f, 15.f, 23.f, 39.f, 71.f, 135.f, 18.f, 29.f, 51.f, 95.f, 183.f};
__device__ constexpr float BAREA[15] = {276.f,1104.f,4416.f,17664.f,70656.f, 256.f,1024.f,4096.f,16384.f,65536.f, 242.f,968.f,3872.f,15488.f,61952.f};

// Same table in constant memory for runtime-indexed access (phase 1)
__constant__ float c_base[60] = {
    -3.5f,   2.f,  18.5f,  13.f,   -15.f,   -4.f,  30.f,   19.f,
   -38.f,  -16.f,  53.f,   31.f,   -84.f,  -40.f,  99.f,   55.f,
  -176.f,  -88.f, 191.f,  103.f,     0.f,    0.f,  15.f,   15.f,
    -8.f,   -8.f,  23.f,   23.f,   -24.f,  -24.f,  39.f,   39.f,
   -56.f,  -56.f,  71.f,   71.f,  -120.f, -120.f, 135.f,  135.f,
     2.5f,  -3.f,  12.5f,  18.f,    -3.f,  -14.f,  18.f,   29.f,
   -14.f,  -36.f,  29.f,   51.f,   -36.f,  -80.f,  51.f,   95.f,
   -80.f, -168.f,  95.f,  183.f
};

__device__ int g_bp[MAX_P1];
__device__ int g_bn[MAX_P1];
__device__ int g_win[MAX_G];
__device__ unsigned g_bar_count = 0;
__device__ volatile unsigned g_bar_gen = 0;

// Software grid barrier. Valid: all blocks co-resident (grid = 2 * #SMs, occ 2).
__device__ __forceinline__ void grid_barrier(int nblocks) {
    __syncthreads();
    if (threadIdx.x == 0) {
        __threadfence();
        unsigned gen = g_bar_gen;
        if (atomicAdd(&g_bar_count, 1u) == (unsigned)(nblocks - 1)) {
            atomicExch(&g_bar_count, 0u);
            __threadfence();
            g_bar_gen = gen + 1;
        } else {
            while (g_bar_gen == gen) { }
        }
        __threadfence();
    }
    __syncthreads();
}

__global__ void __launch_bounds__(TPB, 2)
k_fused(const float* __restrict__ gt, const float* __restrict__ meta,
        float* __restrict__ out, int K, int r, int c, int G,
        int nblocks, int nP1, int chunk, float inv_c) {
    __shared__ float4 s_gt[MAX_G];
    __shared__ float  s_area[MAX_G];
    __shared__ int    s_wp[NW], s_wn[NW];
    __shared__ float  s_ri[NW], s_rd[NW];
    __shared__ int    s_rk[NW];
    __shared__ int    s_sp[MAX_P1], s_sn[MAX_P1];

    const int tid  = threadIdx.x;
    const int bid  = blockIdx.x;
    const int lane = tid & 31;
    const int warp = tid >> 5;
    const unsigned FULL = 0xffffffffu;

    for (int g = tid; g < G; g += TPB) {
        float4 b = reinterpret_cast<const float4*>(gt)[g];
        s_gt[g] = b;
        s_area[g] = (b.z - b.x + 1.0f) * (b.w - b.y + 1.0f);
    }
    __syncthreads();

    const float h = meta[0], w = meta[1];
    const float wm1 = w - 1.f, hm1 = h - 1.f;
    float*  lab = out + (size_t)8 * K;
    float4* tgt = reinterpret_cast<float4*>(out + (size_t)4 * K);

    const bool isP1 = (bid < nP1);
    const int base = isP1 ? bid * chunk : 0;
    const int end  = isP1 ? min(base + chunk, K) : 0;
    const float4 gb0 = s_gt[0];

    if (isP1) {
        // ============ Phase 1: per-anchor labels / targets / anchors ======
        for (int sb = base; sb < end; sb += TPB) {
            int k = sb + tid;
            int kk = min(k, end - 1);
            // kk/15 and t2/c via verified float-reciprocal (no int division)
            int t2 = (int)(((float)kk + 0.5f) * (1.0f / 15.0f));
            int a  = kk - t2 * A_NUM;
            int ii = (int)(((float)t2 + 0.5f) * inv_c);
            int jj = t2 - ii * c;
            float sx = (float)(jj << 4);
            float sy = (float)(ii << 4);

            // per-warp spatial window
            float sxlo = sx, sxhi = sx, sylo = sy, syhi = sy;
            #pragma unroll
            for (int off = 16; off; off >>= 1) {
                sxlo = fminf(sxlo, __shfl_xor_sync(FULL, sxlo, off));
                sxhi = fmaxf(sxhi, __shfl_xor_sync(FULL, sxhi, off));
                sylo = fminf(sylo, __shfl_xor_sync(FULL, sylo, off));
                syhi = fmaxf(syhi, __shfl_xor_sync(FULL, syhi, off));
            }
            float xlo = sxlo - 178.f, xhi = sxhi + 193.f;
            float ylo = sylo - 170.f, yhi = syhi + 185.f;

            float x1 = sx + c_base[a * 4 + 0];
            float y1 = sy + c_base[a * 4 + 1];
            float x2 = sx + c_base[a * 4 + 2];
            float y2 = sy + c_base[a * 4 + 3];

            bool valid  = (k < end);
            bool inside = (x1 >= 0.f) && (y1 >= 0.f) && (x2 < w) && (y2 < h);

            if (valid)
                reinterpret_cast<float4*>(out)[k] = make_float4(x1, y1, x2, y2);

            float cx1 = fminf(fmaxf(x1, 0.f), wm1);
            float cy1 = fminf(fmaxf(y1, 0.f), hm1);
            float cx2 = fminf(fmaxf(x2, 0.f), wm1);
            float cy2 = fminf(fmaxf(y2, 0.f), hm1);
            float areaA = (cx2 - cx1 + 1.f) * (cy2 - cy1 + 1.f);

            float bi = 0.f, bd = 1.f;     // matches "all-zero row -> argmax 0"
            int   bg = -1;

            bool need = inside && valid;
            if (__any_sync(FULL, need)) {
                // rounds of 32 gts: candidates live in registers, broadcast by shfl
                for (int gbs = 0; gbs < G; gbs += 32) {
                    int g = gbs + lane;
                    float4 b; float ar = 0.f;
                    bool ok = false;
                    if (g < G) {
                        b = s_gt[g]; ar = s_area[g];
                        ok = (b.y <= yhi) && (b.w >= ylo) && (b.x <= xhi) && (b.z >= xlo);
                    }
                    unsigned m = __ballot_sync(FULL, ok);
                    while (m) {
                        int src = __ffs(m) - 1;
                        m &= m - 1;
                        float bx = __shfl_sync(FULL, b.x, src);
                        float by = __shfl_sync(FULL, b.y, src);
                        float bz = __shfl_sync(FULL, b.z, src);
                        float bw = __shfl_sync(FULL, b.w, src);
                        float ba = __shfl_sync(FULL, ar,  src);
                        float iw = (fminf(cx2, bz) - fmaxf(cx1, bx)) + 1.f;
                        float ih = (fminf(cy2, bw) - fmaxf(cy1, by)) + 1.f;
                        float inter = fmaxf(iw, 0.f) * fmaxf(ih, 0.f);
                        float denom = (areaA + ba) - inter;
                        if (inter * bd > bi * denom) {
                            bi = inter; bd = denom; bg = gbs + src;
                        }
                    }
                }
            }

            if (!valid) continue;
            if (!inside) {
                tgt[k] = make_float4(0.f, 0.f, 0.f, 0.f);
                lab[k] = -1.f;
                continue;
            }

            float mo = __fdiv_rn(bi, bd);   // exact: feeds label thresholds
            float l = -1.f;
            if (mo < 0.3f)  l = 0.f;
            if (mo >= 0.7f) l = 1.f;
            lab[k] = l;

            float4 gb = (bg >= 0) ? s_gt[bg] : gb0;
            float ew = cx2 - cx1 + 1.f, eh = cy2 - cy1 + 1.f;
            float ecx = cx1 + 0.5f * ew, ecy = cy1 + 0.5f * eh;
            float gw = gb.z - gb.x + 1.f, gh = gb.w - gb.y + 1.f;
            float gcx = gb.x + 0.5f * gw, gcy = gb.y + 0.5f * gh;
            tgt[k] = make_float4(__fdividef(gcx - ecx, ew),
                                 __fdividef(gcy - ecy, eh),
                                 __logf(__fdividef(gw, ew)),
                                 __logf(__fdividef(gh, eh)));
        }
    } else {
        // ============ Phase 2 (concurrent): per-gt argmax ================
        for (int g = bid - nP1; g < G; g += nblocks - nP1) {
            float4 b = s_gt[g];
            float areaB = s_area[g];

            int j0 = max(0,     (int)floorf((b.x - 193.f) * 0.0625f) - 1);
            int j1 = min(c - 1, (int)ceilf ((b.z + 178.f) * 0.0625f) + 1);
            int i0 = max(0,     (int)floorf((b.y - 185.f) * 0.0625f) - 1);
            int i1 = min(r - 1, (int)ceilf ((b.w + 170.f) * 0.0625f) + 1);
            int nj = j1 - j0 + 1;
            int ncells = nj * (i1 - i0 + 1);
            float inv_nj = 1.0f / (float)nj;   // full-precision, once per gt

            float bi = -1.f, bd = 1.f;
            int   bk = 0x7fffffff;

            for (int t = tid; t < ncells; t += TPB) {
                int dv = (int)(((float)t + 0.5f) * inv_nj);
                int jj = j0 + (t - dv * nj);
                int ii = i0 + dv;
                float sx = (float)(jj << 4);
                float sy = (float)(ii << 4);
                int kbase = (ii * c + jj) * A_NUM;
                #pragma unroll
                for (int a = 0; a < A_NUM; a++) {
                    float x1 = sx + BAX1[a];
                    float y1 = sy + BAY1[a];
                    float x2 = sx + BAX2[a];
                    float y2 = sy + BAY2[a];
                    bool ins = (x1 >= 0.f) && (y1 >= 0.f) && (x2 < w) && (y2 < h);
                    float iw = (fminf(x2, b.z) - fmaxf(x1, b.x)) + 1.f;
                    float ih = (fminf(y2, b.w) - fmaxf(y1, b.y)) + 1.f;
                    float inter = fmaxf(iw, 0.f) * fmaxf(ih, 0.f);
                    float denom = (BAREA[a] + areaB) - inter;
                    int k = kbase + a;
                    float p1 = inter * bd, p2 = bi * denom;
                    if (ins && (p1 > p2 || (p1 == p2 && k < bk))) {
                        bi = inter; bd = denom; bk = k;
                    }
                }
            }

            #pragma unroll
            for (int off = 16; off; off >>= 1) {
                float oi = __shfl_down_sync(FULL, bi, off);
                float od = __shfl_down_sync(FULL, bd, off);
                int   ok = __shfl_down_sync(FULL, bk, off);
                float p1 = oi * bd, p2 = bi * od;
                if (p1 > p2 || (p1 == p2 && ok < bk)) { bi = oi; bd = od; bk = ok; }
            }
            if (lane == 0) { s_ri[warp] = bi; s_rd[warp] = bd; s_rk[warp] = bk; }
            __syncthreads();
            if (warp == 0) {
                bi = (lane < NW) ? s_ri[lane] : -1.f;
                bd = (lane < NW) ? s_rd[lane] : 1.f;
                bk = (lane < NW) ? s_rk[lane] : 0x7fffffff;
                #pragma unroll
                for (int off = 16; off; off >>= 1) {
                    float oi = __shfl_down_sync(FULL, bi, off);
                    float od = __shfl_down_sync(FULL, bd, off);
                    int   ok = __shfl_down_sync(FULL, bk, off);
                    float p1 = oi * bd, p2 = bi * od;
                    if (p1 > p2 || (p1 == p2 && ok < bk)) { bi = oi; bd = od; bk = ok; }
                }
                if (lane == 0) g_win[g] = bk;   // ordered by barrier fence
            }
            __syncthreads();
        }
    }

    grid_barrier(nblocks);

    if (isP1) {
        // ---- apply winners that fall in my chunk, then count -------------
        if (tid < G) {
            int kw = __ldcg(&g_win[tid]);
            if (kw >= base && kw < end) lab[kw] = 1.0f;
        }
        __syncthreads();

        int cp = 0, cn = 0;
        for (int k = base + tid; k < end; k += TPB) {
            float l = lab[k];               // own block wrote everything here
            cp += (l == 1.f);
            cn += (l == 0.f);
        }
        #pragma unroll
        for (int off = 16; off; off >>= 1) {
            cp += __shfl_down_sync(FULL, cp, off);
            cn += __shfl_down_sync(FULL, cn, off);
        }
        if (lane == 0) { s_wp[warp] = cp; s_wn[warp] = cn; }
        __syncthreads();
        if (tid == 0) {
            int p = 0, n = 0;
            #pragma unroll
            for (int v = 0; v < NW; v++) { p += s_wp[v]; n += s_wn[v]; }
            g_bp[bid] = p; g_bn[bid] = n;
        }
    }

    grid_barrier(nblocks);
    if (!isP1) return;

    // ---- shfl-based scan of block counts + apply subsampling -------------
    int vp = (tid < nP1) ? __ldcg(&g_bp[tid]) : 0;
    int vn = (tid < nP1) ? __ldcg(&g_bn[tid]) : 0;
    #pragma unroll
    for (int off = 1; off < 32; off <<= 1) {
        int tp = __shfl_up_sync(FULL, vp, off);
        int tn = __shfl_up_sync(FULL, vn, off);
        if (lane >= off) { vp += tp; vn += tn; }
    }
    if (lane == 31) { s_wp[warp] = vp; s_wn[warp] = vn; }
    __syncthreads();
    if (warp == 0 && lane < NW) {
        int wv = s_wp[lane], wn2 = s_wn[lane];
        #pragma unroll
        for (int off = 1; off < NW; off <<= 1) {
            int tp = __shfl_up_sync(0xffffu, wv, off);
            int tn = __shfl_up_sync(0xffffu, wn2, off);
            if (lane >= off) { wv += tp; wn2 += tn; }
        }
        s_wp[lane] = wv; s_wn[lane] = wn2;
    }
    __syncthreads();
    if (warp > 0) { vp += s_wp[warp - 1]; vn += s_wn[warp - 1]; }
    s_sp[tid] = vp; s_sn[tid] = vn;
    __syncthreads();

    int runP = (bid > 0) ? s_sp[bid - 1] : 0;
    int runN = (bid > 0) ? s_sn[bid - 1] : 0;
    int totP = s_sp[nP1 - 1];
    const int numBg = RPN_BATCH_C - (totP < NUM_FG ? totP : NUM_FG);
    __syncthreads();

    for (int s = base; s < end; s += TPB) {
        int k = s + tid;
        float l = (k < end) ? lab[k] : -1.f;
        int pos = (l == 1.f);
        int neg = (l == 0.f);
        unsigned ballp = __ballot_sync(FULL, pos);
        unsigned balln = __ballot_sync(FULL, neg);
        if (lane == 0) { s_wp[warp] = __popc(ballp); s_wn[warp] = __popc(balln); }
        __syncthreads();
        int wp = 0, wn = 0, totPb = 0, totNb = 0;
        #pragma unroll
        for (int v = 0; v < NW; v++) {
            int a2 = s_wp[v], b2 = s_wn[v];
            if (v < warp) { wp += a2; wn += b2; }
            totPb += a2; totNb += b2;
        }
        unsigned lm = (1u << lane) - 1u;
        int rp = runP + wp + __popc(ballp & lm) + 1;
        int rn = runN + wn + __popc(balln & lm) + 1;
        if (k < end) {
            if (pos && rp > NUM_FG) lab[k] = -1.f;
            if (neg && rn > numBg)  lab[k] = -1.f;
        }
        runP += totPb; runN += totNb;
        __syncthreads();
    }
}

// ---------------------------------------------------------------------------
extern "C" void kernel_launch(void* const* d_in, const int* in_sizes, int n_in,
                              void* d_out, int out_size) {
    const float* gt   = (const float*)d_in[0];
    const float* meta = (const float*)d_in[1];
    float* out = (float*)d_out;

    int G = in_sizes[0] / 4;
    if (G > MAX_G) G = MAX_G;
    int K  = in_sizes[2];
    int rc = K / A_NUM;
    int c  = (int)(sqrt((double)rc) + 0.5);
    int r  = rc / c;
    float inv_c = (float)(1.0 / (double)c);

    int dev = 0;
    cudaGetDevice(&dev);
    int nsm = 0;
    cudaDeviceGetAttribute(&nsm, cudaDevAttrMultiProcessorCount, dev);
    if (nsm <= 0) nsm = 148;
    int nblocks = 2 * nsm;               // 2 co-resident blocks per SM
    int nP1 = nblocks - G;               // dedicated phase-1 blocks
    if (nP1 < nblocks / 2) nP1 = nblocks / 2;
    if (nP1 > MAX_P1) nP1 = MAX_P1;
    int chunk = (K + nP1 - 1) / nP1;

    k_fused<<<nblocks, TPB>>>(gt, meta, out, K, r, c, G, nblocks, nP1, chunk, inv_c);
}